// round 14
// baseline (speedup 1.0000x reference)
#include <cuda_runtime.h>
#include <math.h>

// ---------------------------------------------------------------------------
// Differentiable JPEG (quality 80) forward pass, fused single kernel.
// Tile = 32x16 px, CTA = 128 threads; each thread owns a 1x4 row segment.
// Y path is ROW-FIRST: horizontal fwd DCT fused into the pixel phase (row
// assembled from the c^1 partner via shfl_xor(1)); middle epoch = vertical
// fwd + quant + vertical inv per column; horizontal inverse fused into
// writeback. Y shared traffic: 2 round trips instead of 4.
// Chroma (4 blocks): classic 3-stage pipeline (A shares the main epoch).
// Quant tables interleaved conflict-free; Y table transposed ([v][u]).
// ---------------------------------------------------------------------------

#define IMG 512

__constant__ float c_YTAB[64] = {
    16,11,10,16,24,40,51,61,  12,12,14,19,26,58,60,55,
    14,13,16,24,40,57,69,56,  14,17,22,29,51,87,80,62,
    18,22,37,56,68,109,103,77, 24,35,55,64,81,104,113,92,
    49,64,78,87,103,121,120,101, 72,92,95,98,112,100,103,99};
__constant__ float c_CTAB[64] = {
    17,18,24,47,99,99,99,99,  18,21,26,66,99,99,99,99,
    24,26,56,99,99,99,99,99,  47,66,99,99,99,99,99,99,
    99,99,99,99,99,99,99,99,  99,99,99,99,99,99,99,99,
    99,99,99,99,99,99,99,99,  99,99,99,99,99,99,99,99};

// cos(k*pi/16)
#define C1 0.980785280403230449f
#define C2 0.923879532511286756f
#define C3 0.831469612302545237f
#define C4 0.707106781186547524f
#define C5 0.555570233019602225f
#define C6 0.382683432365089772f
#define C7 0.195090322016128268f
#define RSQRT2 0.70710678118654752f

__device__ __forceinline__ void dct8_fwd(const float in[8], float a[8]) {
    float s0 = in[0] + in[7], s1 = in[1] + in[6];
    float s2 = in[2] + in[5], s3 = in[3] + in[4];
    float d0 = in[0] - in[7], d1 = in[1] - in[6];
    float d2 = in[2] - in[5], d3 = in[3] - in[4];
    a[0] = (s0 + s3) + (s1 + s2);
    a[2] = C2 * s0 + C6 * s1 - C6 * s2 - C2 * s3;
    a[4] = C4 * ((s0 + s3) - (s1 + s2));
    a[6] = C6 * s0 - C2 * s1 + C2 * s2 - C6 * s3;
    a[1] = C1 * d0 + C3 * d1 + C5 * d2 + C7 * d3;
    a[3] = C3 * d0 - C7 * d1 - C1 * d2 - C5 * d3;
    a[5] = C5 * d0 - C1 * d1 + C7 * d2 + C3 * d3;
    a[7] = C7 * d0 - C5 * d1 + C3 * d2 - C1 * d3;
}

__device__ __forceinline__ void dct8_inv(const float h[8], float p[8]) {
    float e0 = h[0] + C2 * h[2] + C4 * h[4] + C6 * h[6];
    float e1 = h[0] + C6 * h[2] - C4 * h[4] - C2 * h[6];
    float e2 = h[0] - C6 * h[2] - C4 * h[4] + C2 * h[6];
    float e3 = h[0] - C2 * h[2] + C4 * h[4] - C6 * h[6];
    float o0 = C1 * h[1] + C3 * h[3] + C5 * h[5] + C7 * h[7];
    float o1 = C3 * h[1] - C7 * h[3] - C1 * h[5] - C5 * h[7];
    float o2 = C5 * h[1] - C1 * h[3] + C7 * h[5] + C3 * h[7];
    float o3 = C7 * h[1] - C5 * h[3] + C3 * h[5] - C1 * h[7];
    p[0] = e0 + o0;  p[7] = e0 - o0;
    p[1] = e1 + o1;  p[6] = e1 - o1;
    p[2] = e2 + o2;  p[5] = e2 - o2;
    p[3] = e3 + o3;  p[4] = e3 - o3;
}

__global__ void __launch_bounds__(128)
jpeg_tile_kernel(const float* __restrict__ img, float* __restrict__ out) {
    __shared__ float sAqY[64], sBqY[64];  // Y quant, TRANSPOSED interleaved [v][u]
    __shared__ float sAqC[64], sBqC[64];  // chroma quant, interleaved [u][v]
    __shared__ float s1[12][8][9];   // 0..7 Y, 8..9 Cb, 10..11 Cr
    __shared__ float s2[12][8][9];

    const int t = threadIdx.x;

    if (t < 64) {
        int u = t >> 3, v = t & 7;
        float au = (u == 0) ? RSQRT2 : 1.f;
        float av = (v == 0) ? RSQRT2 : 1.f;
        float S = au * av * 0.25f;
        float qy = c_YTAB[t] * 0.4f;   // QUALITY=80 -> FACTOR=0.4
        float qc = c_CTAB[t] * 0.4f;
        int wY = v * 4 + (u & 3) + ((u >> 2) << 5);   // transposed interleave
        int wC = u * 4 + (v & 3) + ((v >> 2) << 5);   // normal interleave
        sAqY[wY] = __fdividef(S, qy);  sBqY[wY] = S * qy;
        sAqC[wC] = __fdividef(S, qc);  sBqC[wC] = S * qc;
    }

    const int tile = blockIdx.x;
    const int tx   = tile & 15;          // 16 tiles across (32 px each)
    const int ty   = (tile >> 4) & 31;   // 32 tiles down (16 px each)
    const int bimg = tile >> 9;

    const int c = t & 7;                 // 4-px group 0..7 (32 px across)
    const int r = t >> 3;                // tile row 0..15
    const int px0 = tx * 32 + c * 4;
    const int py  = ty * 16 + r;

    const size_t plane = (size_t)IMG * IMG;
    const float* base = img + (size_t)bimg * 3 * plane + (size_t)py * IMG + px0;

    const int yblk = ((r >> 3) << 2) + (c >> 1);    // 4 across x 2 down
    const int ycol = (c & 1) * 4;                   // which half of the row
    const int yrow = r & 7;
    const int cbB  = c >> 2;
    const int ccol = (c * 2) & 7;
    const int crow = r >> 1;

    // ---- E1: load, color-convert, Y horizontal DCT (row via shfl), stage.
    float4 Rv4 = *(const float4*)(base);
    float4 Gv4 = *(const float4*)(base + plane);
    float4 Bv4 = *(const float4*)(base + 2 * plane);
    float Ra[4] = {Rv4.x, Rv4.y, Rv4.z, Rv4.w};
    float Ga[4] = {Gv4.x, Gv4.y, Gv4.z, Gv4.w};
    float Ba[4] = {Bv4.x, Bv4.y, Bv4.z, Bv4.w};

    float y4[4], cbp[2], crp[2];
    #pragma unroll
    for (int k = 0; k < 4; k++) {
        float rr = Ra[k] * 255.f, gg = Ga[k] * 255.f, bb = Ba[k] * 255.f;
        y4[k] = 0.299f * rr + 0.587f * gg + 0.114f * bb - 128.f;  // -128 folded
        float cbv = -0.042184f * rr - 0.082816f * gg + 0.125f    * bb;  // /4 folded
        float crv =  0.125f    * rr - 0.104672f * gg - 0.020328f * bb;
        if ((k & 1) == 0) { cbp[k >> 1] = cbv;  crp[k >> 1] = crv; }
        else              { cbp[k >> 1] += cbv; crp[k >> 1] += crv; }
    }
    // chroma vertical pair: rows r, r^1 are lanes t, t^8 (same warp)
    #pragma unroll
    for (int k = 0; k < 2; k++) {
        cbp[k] += __shfl_xor_sync(0xFFFFFFFFu, cbp[k], 8);
        crp[k] += __shfl_xor_sync(0xFFFFFFFFu, crp[k], 8);
    }
    // Y: assemble the full 8-px row from partner lane t^1
    float yrow8[8];
    #pragma unroll
    for (int k = 0; k < 4; k++) {
        float recv = __shfl_xor_sync(0xFFFFFFFFu, y4[k], 1);
        if ((c & 1) == 0) { yrow8[k] = y4[k];  yrow8[4 + k] = recv; }
        else              { yrow8[k] = recv;   yrow8[4 + k] = y4[k]; }
    }
    {
        float a[8];
        dct8_fwd(yrow8, a);                     // horizontal fwd DCT in regs
        #pragma unroll
        for (int k = 0; k < 4; k++)             // write this thread's half
            s1[yblk][yrow][ycol + k] = a[ycol + k];
    }
    if ((r & 1) == 0) {                         // chroma pixel-domain staging
        #pragma unroll
        for (int k = 0; k < 2; k++) {
            s1[8  + cbB][crow][ccol + k] = cbp[k];
            s1[10 + cbB][crow][ccol + k] = crp[k];
        }
    }
    __syncthreads();

    // ---- E2: 96 tasks. Y (blk<8): vertical fwd + quant + vertical inv on
    //      coefficient column v. Chroma (blk 8..11): classic stage A.
    if (t < 96) {
        int blk = t >> 3, v = t & 7;
        if (blk < 8) {
            float col[8];
            #pragma unroll
            for (int y = 0; y < 8; y++) col[y] = s1[blk][y][v];
            float cu[8];
            dct8_fwd(col, cu);                  // vertical fwd -> full 2D coef

            // transposed table: u-vector for fixed v
            const float4 qa0 = *(const float4*)&sAqY[v * 4];
            const float4 qa1 = *(const float4*)&sAqY[v * 4 + 32];
            const float4 qb0 = *(const float4*)&sBqY[v * 4];
            const float4 qb1 = *(const float4*)&sBqY[v * 4 + 32];
            const float Aq[8] = {qa0.x, qa0.y, qa0.z, qa0.w, qa1.x, qa1.y, qa1.z, qa1.w};
            const float Bq[8] = {qb0.x, qb0.y, qb0.z, qb0.w, qb1.x, qb1.y, qb1.z, qb1.w};

            float h[8];
            #pragma unroll
            for (int u = 0; u < 8; u++) {
                float cc = cu[u] * Aq[u];
                float rr = rintf(cc);           // round-half-even == jnp.round
                float dd = cc - rr;
                h[u] = (rr + dd * dd * dd) * Bq[u];
            }
            float hy[8];
            dct8_inv(h, hy);                    // vertical inverse
            #pragma unroll
            for (int y = 0; y < 8; y++) s2[blk][y][v] = hy[y];
        } else {
            int j = v;
            float in[8], a[8];
            #pragma unroll
            for (int x = 0; x < 8; x++) in[x] = s1[blk][x][j];
            dct8_fwd(in, a);                    // chroma vertical fwd
            #pragma unroll
            for (int u = 0; u < 8; u++) s2[blk][u][j] = a[u];
        }
    }
    __syncthreads();

    // ---- E2b: chroma stage B (32 tasks): horizontal fwd + quant + inv.
    if (t < 32) {
        int blk = 8 + (t >> 3), u = t & 7;
        float row[8], cv[8];
        #pragma unroll
        for (int y = 0; y < 8; y++) row[y] = s2[blk][u][y];
        dct8_fwd(row, cv);

        const float4 qa0 = *(const float4*)&sAqC[u * 4];
        const float4 qa1 = *(const float4*)&sAqC[u * 4 + 32];
        const float4 qb0 = *(const float4*)&sBqC[u * 4];
        const float4 qb1 = *(const float4*)&sBqC[u * 4 + 32];
        const float Aq[8] = {qa0.x, qa0.y, qa0.z, qa0.w, qa1.x, qa1.y, qa1.z, qa1.w};
        const float Bq[8] = {qb0.x, qb0.y, qb0.z, qb0.w, qb1.x, qb1.y, qb1.z, qb1.w};

        float h[8];
        #pragma unroll
        for (int v = 0; v < 8; v++) {
            float cc = cv[v] * Aq[v];
            float rr = rintf(cc);
            float dd = cc - rr;
            h[v] = (rr + dd * dd * dd) * Bq[v];
        }
        float p[8];
        dct8_inv(h, p);
        #pragma unroll
        for (int y = 0; y < 8; y++) s1[blk][u][y] = p[y];
    }
    __syncthreads();

    // ---- E2c: chroma stage C (32 tasks): vertical inverse -> pixel domain.
    if (t < 32) {
        int blk = 8 + (t >> 3), j = t & 7;
        float in[8], p[8];
        #pragma unroll
        for (int u = 0; u < 8; u++) in[u] = s1[blk][u][j];
        dct8_inv(in, p);
        #pragma unroll
        for (int x = 0; x < 8; x++) s2[blk][x][j] = p[x];   // +-128 cancels
    }
    __syncthreads();

    // ---- E3: Y horizontal inverse in regs, chroma read, color, store.
    float hrow[8];
    #pragma unroll
    for (int j = 0; j < 8; j++) hrow[j] = s2[yblk][yrow][j];
    float yp[8];
    dct8_inv(hrow, yp);                         // horizontal inverse

    float cbv2[2], crv2[2];
    #pragma unroll
    for (int k = 0; k < 2; k++) {
        cbv2[k] = s2[8  + cbB][crow][ccol + k];
        crv2[k] = s2[10 + cbB][crow][ccol + k];
    }

    float Ro[4], Go[4], Bo[4];
    #pragma unroll
    for (int k = 0; k < 4; k++) {
        float yy = yp[ycol + k] + 128.f;
        float cb = cbv2[k >> 1];
        float cr = crv2[k >> 1];
        float rr = yy + 1.402f * cr;
        float gg = yy - 0.344136f * cb - 0.714136f * cr;
        float bb = yy + 1.772f * cb;
        Ro[k] = fminf(fmaxf(rr, 0.f), 255.f) * (1.f / 255.f);
        Go[k] = fminf(fmaxf(gg, 0.f), 255.f) * (1.f / 255.f);
        Bo[k] = fminf(fmaxf(bb, 0.f), 255.f) * (1.f / 255.f);
    }
    float* op = out + (size_t)bimg * 3 * plane + (size_t)py * IMG + px0;
    *(float4*)(op)             = make_float4(Ro[0], Ro[1], Ro[2], Ro[3]);
    *(float4*)(op + plane)     = make_float4(Go[0], Go[1], Go[2], Go[3]);
    *(float4*)(op + 2 * plane) = make_float4(Bo[0], Bo[1], Bo[2], Bo[3]);
}

extern "C" void kernel_launch(void* const* d_in, const int* in_sizes, int n_in,
                              void* d_out, int out_size) {
    const float* img = (const float*)d_in[0];
    float* out = (float*)d_out;
    int batch = in_sizes[0] / (3 * IMG * IMG);         // 32
    int tiles = batch * (IMG / 16) * (IMG / 32);       // 16384
    jpeg_tile_kernel<<<tiles, 128>>>(img, out);
}

// round 15
// speedup vs baseline: 1.1005x; 1.1005x over previous
#include <cuda_runtime.h>
#include <math.h>

// ---------------------------------------------------------------------------
// Differentiable JPEG (quality 80) forward pass, fused single kernel.
// Tile = 32x16 px, CTA = 128 threads; each thread owns a 1x4 row segment.
// Global I/O: float4. Shared staging: scalar on the proven [8][9] layout.
// Stages A->B->C flow each 8x8 block through ONE 8-thread octet, so the
// inter-stage syncs are warp-local (__syncwarp), not CTA barriers. Only
// pixel->A and C->writeback need __syncthreads.
// Quant tables interleaved conflict-free; chroma coefficients prescaled.
// ---------------------------------------------------------------------------

#define IMG 512

__constant__ float c_YTAB[64] = {
    16,11,10,16,24,40,51,61,  12,12,14,19,26,58,60,55,
    14,13,16,24,40,57,69,56,  14,17,22,29,51,87,80,62,
    18,22,37,56,68,109,103,77, 24,35,55,64,81,104,113,92,
    49,64,78,87,103,121,120,101, 72,92,95,98,112,100,103,99};
__constant__ float c_CTAB[64] = {
    17,18,24,47,99,99,99,99,  18,21,26,66,99,99,99,99,
    24,26,56,99,99,99,99,99,  47,66,99,99,99,99,99,99,
    99,99,99,99,99,99,99,99,  99,99,99,99,99,99,99,99,
    99,99,99,99,99,99,99,99,  99,99,99,99,99,99,99,99};

// cos(k*pi/16)
#define C1 0.980785280403230449f
#define C2 0.923879532511286756f
#define C3 0.831469612302545237f
#define C4 0.707106781186547524f
#define C5 0.555570233019602225f
#define C6 0.382683432365089772f
#define C7 0.195090322016128268f
#define RSQRT2 0.70710678118654752f

__device__ __forceinline__ void dct8_fwd(const float in[8], float a[8]) {
    float s0 = in[0] + in[7], s1 = in[1] + in[6];
    float s2 = in[2] + in[5], s3 = in[3] + in[4];
    float d0 = in[0] - in[7], d1 = in[1] - in[6];
    float d2 = in[2] - in[5], d3 = in[3] - in[4];
    a[0] = (s0 + s3) + (s1 + s2);
    a[2] = C2 * s0 + C6 * s1 - C6 * s2 - C2 * s3;
    a[4] = C4 * ((s0 + s3) - (s1 + s2));
    a[6] = C6 * s0 - C2 * s1 + C2 * s2 - C6 * s3;
    a[1] = C1 * d0 + C3 * d1 + C5 * d2 + C7 * d3;
    a[3] = C3 * d0 - C7 * d1 - C1 * d2 - C5 * d3;
    a[5] = C5 * d0 - C1 * d1 + C7 * d2 + C3 * d3;
    a[7] = C7 * d0 - C5 * d1 + C3 * d2 - C1 * d3;
}

__device__ __forceinline__ void dct8_inv(const float h[8], float p[8]) {
    float e0 = h[0] + C2 * h[2] + C4 * h[4] + C6 * h[6];
    float e1 = h[0] + C6 * h[2] - C4 * h[4] - C2 * h[6];
    float e2 = h[0] - C6 * h[2] - C4 * h[4] + C2 * h[6];
    float e3 = h[0] - C2 * h[2] + C4 * h[4] - C6 * h[6];
    float o0 = C1 * h[1] + C3 * h[3] + C5 * h[5] + C7 * h[7];
    float o1 = C3 * h[1] - C7 * h[3] - C1 * h[5] - C5 * h[7];
    float o2 = C5 * h[1] - C1 * h[3] + C7 * h[5] + C3 * h[7];
    float o3 = C7 * h[1] - C5 * h[3] + C3 * h[5] - C1 * h[7];
    p[0] = e0 + o0;  p[7] = e0 - o0;
    p[1] = e1 + o1;  p[6] = e1 - o1;
    p[2] = e2 + o2;  p[5] = e2 - o2;
    p[3] = e3 + o3;  p[4] = e3 - o3;
}

__global__ void __launch_bounds__(128)
jpeg_tile_kernel(const float* __restrict__ img, float* __restrict__ out) {
    __shared__ float sAq[2][64];     // (ALPHA*0.25)/q, interleaved layout
    __shared__ float sBq[2][64];     // (ALPHA*0.25)*q, interleaved layout
    __shared__ float s1[12][8][9];   // blocks 0..7 = Y, 8..9 = Cb, 10..11 = Cr
    __shared__ float s2[12][8][9];

    const int t = threadIdx.x;

    if (t < 64) {
        int u = t >> 3, v = t & 7;
        float au = (u == 0) ? RSQRT2 : 1.f;
        float av = (v == 0) ? RSQRT2 : 1.f;
        float S = au * av * 0.25f;
        float qy = c_YTAB[t] * 0.4f;   // QUALITY=80 -> FACTOR=0.4
        float qc = c_CTAB[t] * 0.4f;
        // interleaved: word = u*4 + (v&3) + (v>>2)*32 -> LDS.128 at u*4 is
        // conflict-free across u (words 0..31 each hit once)
        int w = u * 4 + (v & 3) + ((v >> 2) << 5);
        sAq[0][w] = __fdividef(S, qy);  sBq[0][w] = S * qy;
        sAq[1][w] = __fdividef(S, qc);  sBq[1][w] = S * qc;
    }

    const int tile = blockIdx.x;
    const int tx   = tile & 15;          // 16 tiles across (32 px each)
    const int ty   = (tile >> 4) & 31;   // 32 tiles down (16 px each)
    const int bimg = tile >> 9;

    const int c = t & 7;                 // 4-px group 0..7 (32 px across)
    const int r = t >> 3;                // tile row 0..15
    const int px0 = tx * 32 + c * 4;
    const int py  = ty * 16 + r;

    const size_t plane = (size_t)IMG * IMG;
    const float* base = img + (size_t)bimg * 3 * plane + (size_t)py * IMG + px0;

    // Y block / position for this segment
    const int yblk = ((r >> 3) << 2) + (c >> 1);    // 4 across x 2 down
    const int ycol = (c & 1) * 4;
    const int yrow = r & 7;
    // Chroma block/col for this segment's 2 averaged px
    const int cbB  = c >> 2;                        // 0..1
    const int ccol = (c * 2) & 7;                   // 0,2,4,6 pattern
    const int crow = r >> 1;

    // ---- Pixel phase: float4 RGB loads, color-convert, scalar staging.
    float4 Rv4 = *(const float4*)(base);
    float4 Gv4 = *(const float4*)(base + plane);
    float4 Bv4 = *(const float4*)(base + 2 * plane);
    float Ra[4] = {Rv4.x, Rv4.y, Rv4.z, Rv4.w};
    float Ga[4] = {Gv4.x, Gv4.y, Gv4.z, Gv4.w};
    float Ba[4] = {Bv4.x, Bv4.y, Bv4.z, Bv4.w};

    float y4[4], cbp[2], crp[2];
    #pragma unroll
    for (int k = 0; k < 4; k++) {
        float rr = Ra[k] * 255.f, gg = Ga[k] * 255.f, bb = Ba[k] * 255.f;
        y4[k] = 0.299f * rr + 0.587f * gg + 0.114f * bb - 128.f;  // -128 folded
        // chroma coefficients prescaled by 0.25 (exact exponent shift)
        float cbv = -0.042184f * rr - 0.082816f * gg + 0.125f    * bb;
        float crv =  0.125f    * rr - 0.104672f * gg - 0.020328f * bb;
        if ((k & 1) == 0) { cbp[k >> 1] = cbv;  crp[k >> 1] = crv; }
        else              { cbp[k >> 1] += cbv; crp[k >> 1] += crv; }
    }
    // vertical pair: rows r, r^1 are lanes t, t^8 (same warp)
    #pragma unroll
    for (int k = 0; k < 2; k++) {
        cbp[k] += __shfl_xor_sync(0xFFFFFFFFu, cbp[k], 8);
        crp[k] += __shfl_xor_sync(0xFFFFFFFFu, crp[k], 8);
    }
    #pragma unroll
    for (int k = 0; k < 4; k++) s1[yblk][yrow][ycol + k] = y4[k];
    if ((r & 1) == 0) {
        #pragma unroll
        for (int k = 0; k < 2; k++) {
            s1[8  + cbB][crow][ccol + k] = cbp[k];
            s1[10 + cbB][crow][ccol + k] = crp[k];
        }
    }
    __syncthreads();   // CTA-wide: pixel staging crosses warps

    // ---- Stages A/B/C: each block lives in ONE octet across all stages,
    //      so inter-stage sync is warp-local.
    if (t < 96) {
        const int blk = t >> 3;
        const int ti  = (blk < 8) ? 0 : 1;
        const int lane = t & 7;            // column j in A/C, row u in B

        // Stage A: vertical DCT on column `lane`
        {
            float in[8], a[8];
            #pragma unroll
            for (int x = 0; x < 8; x++) in[x] = s1[blk][x][lane];
            dct8_fwd(in, a);
            #pragma unroll
            for (int u = 0; u < 8; u++) s2[blk][u][lane] = a[u];
        }
        __syncwarp();

        // Stage B: horizontal DCT + diff_round quant + horizontal IDCT on row `lane`
        {
            const int u = lane;
            float row[8], cv[8];
            #pragma unroll
            for (int y = 0; y < 8; y++) row[y] = s2[blk][u][y];
            dct8_fwd(row, cv);

            const float4 qa0 = *(const float4*)&sAq[ti][u * 4];
            const float4 qa1 = *(const float4*)&sAq[ti][u * 4 + 32];
            const float4 qb0 = *(const float4*)&sBq[ti][u * 4];
            const float4 qb1 = *(const float4*)&sBq[ti][u * 4 + 32];
            const float Aq[8]  = {qa0.x, qa0.y, qa0.z, qa0.w, qa1.x, qa1.y, qa1.z, qa1.w};
            const float Bq2[8] = {qb0.x, qb0.y, qb0.z, qb0.w, qb1.x, qb1.y, qb1.z, qb1.w};

            float h[8];
            #pragma unroll
            for (int v = 0; v < 8; v++) {
                float cc = cv[v] * Aq[v];
                float rr = rintf(cc);             // round-half-even == jnp.round
                float dd = cc - rr;
                h[v] = (rr + dd * dd * dd) * Bq2[v];
            }
            float p[8];
            dct8_inv(h, p);
            #pragma unroll
            for (int y = 0; y < 8; y++) s1[blk][u][y] = p[y];
        }
        __syncwarp();

        // Stage C: vertical IDCT on column `lane`
        {
            float in[8], p[8];
            #pragma unroll
            for (int u = 0; u < 8; u++) in[u] = s1[blk][u][lane];
            dct8_inv(in, p);
            float add = (blk < 8) ? 128.f : 0.f;   // chroma +128/-128 cancels
            #pragma unroll
            for (int x = 0; x < 8; x++) s2[blk][x][lane] = p[x] + add;
        }
    }
    __syncthreads();   // CTA-wide: writeback reads cross warps

    // ---- Writeback: scalar shared reads, YCbCr->RGB, clip, float4 stores.
    float yv[4], cbv2[2], crv2[2];
    #pragma unroll
    for (int k = 0; k < 4; k++) yv[k] = s2[yblk][yrow][ycol + k];
    #pragma unroll
    for (int k = 0; k < 2; k++) {
        cbv2[k] = s2[8  + cbB][crow][ccol + k];
        crv2[k] = s2[10 + cbB][crow][ccol + k];
    }

    float Ro[4], Go[4], Bo[4];
    #pragma unroll
    for (int k = 0; k < 4; k++) {
        float yy = yv[k];
        float cb = cbv2[k >> 1];
        float cr = crv2[k >> 1];
        float rr = yy + 1.402f * cr;
        float gg = yy - 0.344136f * cb - 0.714136f * cr;
        float bb = yy + 1.772f * cb;
        Ro[k] = fminf(fmaxf(rr, 0.f), 255.f) * (1.f / 255.f);
        Go[k] = fminf(fmaxf(gg, 0.f), 255.f) * (1.f / 255.f);
        Bo[k] = fminf(fmaxf(bb, 0.f), 255.f) * (1.f / 255.f);
    }
    float* op = out + (size_t)bimg * 3 * plane + (size_t)py * IMG + px0;
    *(float4*)(op)             = make_float4(Ro[0], Ro[1], Ro[2], Ro[3]);
    *(float4*)(op + plane)     = make_float4(Go[0], Go[1], Go[2], Go[3]);
    *(float4*)(op + 2 * plane) = make_float4(Bo[0], Bo[1], Bo[2], Bo[3]);
}

extern "C" void kernel_launch(void* const* d_in, const int* in_sizes, int n_in,
                              void* d_out, int out_size) {
    const float* img = (const float*)d_in[0];
    float* out = (float*)d_out;
    int batch = in_sizes[0] / (3 * IMG * IMG);         // 32
    int tiles = batch * (IMG / 16) * (IMG / 32);       // 16384
    jpeg_tile_kernel<<<tiles, 128>>>(img, out);
}

// round 16
// speedup vs baseline: 1.1014x; 1.0008x over previous
#include <cuda_runtime.h>
#include <math.h>

// ---------------------------------------------------------------------------
// Differentiable JPEG (quality 80) forward pass, fused single kernel.
// Tile = 32x16 px, CTA = 128 threads; each thread owns a 1x4 row segment.
// Global I/O: float4. Shared staging: scalar on the proven [8][9] layout.
// Quant tables interleaved conflict-free (word = u*4 + (v&3) + (v>>2)*32).
// Chroma 2x2 average: prescaled coefficients + shfl_xor(8) vertical pairing.
// Final /255 folded into stage C (FADD->FFMA, free), writeback clips [0,1].
// ---------------------------------------------------------------------------

#define IMG 512

__constant__ float c_YTAB[64] = {
    16,11,10,16,24,40,51,61,  12,12,14,19,26,58,60,55,
    14,13,16,24,40,57,69,56,  14,17,22,29,51,87,80,62,
    18,22,37,56,68,109,103,77, 24,35,55,64,81,104,113,92,
    49,64,78,87,103,121,120,101, 72,92,95,98,112,100,103,99};
__constant__ float c_CTAB[64] = {
    17,18,24,47,99,99,99,99,  18,21,26,66,99,99,99,99,
    24,26,56,99,99,99,99,99,  47,66,99,99,99,99,99,99,
    99,99,99,99,99,99,99,99,  99,99,99,99,99,99,99,99,
    99,99,99,99,99,99,99,99,  99,99,99,99,99,99,99,99};

// cos(k*pi/16)
#define C1 0.980785280403230449f
#define C2 0.923879532511286756f
#define C3 0.831469612302545237f
#define C4 0.707106781186547524f
#define C5 0.555570233019602225f
#define C6 0.382683432365089772f
#define C7 0.195090322016128268f
#define RSQRT2 0.70710678118654752f
#define INV255 (1.0f / 255.0f)

__device__ __forceinline__ void dct8_fwd(const float in[8], float a[8]) {
    float s0 = in[0] + in[7], s1 = in[1] + in[6];
    float s2 = in[2] + in[5], s3 = in[3] + in[4];
    float d0 = in[0] - in[7], d1 = in[1] - in[6];
    float d2 = in[2] - in[5], d3 = in[3] - in[4];
    a[0] = (s0 + s3) + (s1 + s2);
    a[2] = C2 * s0 + C6 * s1 - C6 * s2 - C2 * s3;
    a[4] = C4 * ((s0 + s3) - (s1 + s2));
    a[6] = C6 * s0 - C2 * s1 + C2 * s2 - C6 * s3;
    a[1] = C1 * d0 + C3 * d1 + C5 * d2 + C7 * d3;
    a[3] = C3 * d0 - C7 * d1 - C1 * d2 - C5 * d3;
    a[5] = C5 * d0 - C1 * d1 + C7 * d2 + C3 * d3;
    a[7] = C7 * d0 - C5 * d1 + C3 * d2 - C1 * d3;
}

__device__ __forceinline__ void dct8_inv(const float h[8], float p[8]) {
    float e0 = h[0] + C2 * h[2] + C4 * h[4] + C6 * h[6];
    float e1 = h[0] + C6 * h[2] - C4 * h[4] - C2 * h[6];
    float e2 = h[0] - C6 * h[2] - C4 * h[4] + C2 * h[6];
    float e3 = h[0] - C2 * h[2] + C4 * h[4] - C6 * h[6];
    float o0 = C1 * h[1] + C3 * h[3] + C5 * h[5] + C7 * h[7];
    float o1 = C3 * h[1] - C7 * h[3] - C1 * h[5] - C5 * h[7];
    float o2 = C5 * h[1] - C1 * h[3] + C7 * h[5] + C3 * h[7];
    float o3 = C7 * h[1] - C5 * h[3] + C3 * h[5] - C1 * h[7];
    p[0] = e0 + o0;  p[7] = e0 - o0;
    p[1] = e1 + o1;  p[6] = e1 - o1;
    p[2] = e2 + o2;  p[5] = e2 - o2;
    p[3] = e3 + o3;  p[4] = e3 - o3;
}

__global__ void __launch_bounds__(128)
jpeg_tile_kernel(const float* __restrict__ img, float* __restrict__ out) {
    __shared__ float sAq[2][64];     // (ALPHA*0.25)/q, interleaved layout
    __shared__ float sBq[2][64];     // (ALPHA*0.25)*q, interleaved layout
    __shared__ float s1[12][8][9];   // blocks 0..7 = Y, 8..9 = Cb, 10..11 = Cr
    __shared__ float s2[12][8][9];

    const int t = threadIdx.x;

    if (t < 64) {
        int u = t >> 3, v = t & 7;
        float au = (u == 0) ? RSQRT2 : 1.f;
        float av = (v == 0) ? RSQRT2 : 1.f;
        float S = au * av * 0.25f;
        float qy = c_YTAB[t] * 0.4f;   // QUALITY=80 -> FACTOR=0.4
        float qc = c_CTAB[t] * 0.4f;
        // interleaved: word = u*4 + (v&3) + (v>>2)*32 -> LDS.128 at u*4 is
        // conflict-free across u (words 0..31 each hit once)
        int w = u * 4 + (v & 3) + ((v >> 2) << 5);
        sAq[0][w] = __fdividef(S, qy);  sBq[0][w] = S * qy;
        sAq[1][w] = __fdividef(S, qc);  sBq[1][w] = S * qc;
    }

    const int tile = blockIdx.x;
    const int tx   = tile & 15;          // 16 tiles across (32 px each)
    const int ty   = (tile >> 4) & 31;   // 32 tiles down (16 px each)
    const int bimg = tile >> 9;

    const int c = t & 7;                 // 4-px group 0..7 (32 px across)
    const int r = t >> 3;                // tile row 0..15
    const int px0 = tx * 32 + c * 4;
    const int py  = ty * 16 + r;

    const size_t plane = (size_t)IMG * IMG;
    const float* base = img + (size_t)bimg * 3 * plane + (size_t)py * IMG + px0;

    // Y block / position for this segment
    const int yblk = ((r >> 3) << 2) + (c >> 1);    // 4 across x 2 down
    const int ycol = (c & 1) * 4;
    const int yrow = r & 7;
    // Chroma block/col for this segment's 2 averaged px
    const int cbB  = c >> 2;                        // 0..1
    const int ccol = (c * 2) & 7;                   // 0,2,4,6 pattern
    const int crow = r >> 1;

    // ---- Pixel phase: float4 RGB loads, color-convert, scalar staging.
    float4 Rv4 = *(const float4*)(base);
    float4 Gv4 = *(const float4*)(base + plane);
    float4 Bv4 = *(const float4*)(base + 2 * plane);
    float Ra[4] = {Rv4.x, Rv4.y, Rv4.z, Rv4.w};
    float Ga[4] = {Gv4.x, Gv4.y, Gv4.z, Gv4.w};
    float Ba[4] = {Bv4.x, Bv4.y, Bv4.z, Bv4.w};

    float y4[4], cbp[2], crp[2];
    #pragma unroll
    for (int k = 0; k < 4; k++) {
        float rr = Ra[k] * 255.f, gg = Ga[k] * 255.f, bb = Ba[k] * 255.f;
        y4[k] = 0.299f * rr + 0.587f * gg + 0.114f * bb - 128.f;  // -128 folded
        // chroma coefficients prescaled by 0.25 (exact exponent shift)
        float cbv = -0.042184f * rr - 0.082816f * gg + 0.125f    * bb;
        float crv =  0.125f    * rr - 0.104672f * gg - 0.020328f * bb;
        if ((k & 1) == 0) { cbp[k >> 1] = cbv;  crp[k >> 1] = crv; }
        else              { cbp[k >> 1] += cbv; crp[k >> 1] += crv; }
    }
    // vertical pair: rows r, r^1 are lanes t, t^8 (same warp)
    #pragma unroll
    for (int k = 0; k < 2; k++) {
        cbp[k] += __shfl_xor_sync(0xFFFFFFFFu, cbp[k], 8);
        crp[k] += __shfl_xor_sync(0xFFFFFFFFu, crp[k], 8);
    }
    #pragma unroll
    for (int k = 0; k < 4; k++) s1[yblk][yrow][ycol + k] = y4[k];
    if ((r & 1) == 0) {
        #pragma unroll
        for (int k = 0; k < 2; k++) {
            s1[8  + cbB][crow][ccol + k] = cbp[k];
            s1[10 + cbB][crow][ccol + k] = crp[k];
        }
    }
    __syncthreads();

    // ---- Stage A: vertical DCT: s2[b][u][j] = sum_x CT[x][u]*s1[b][x][j]
    if (t < 96) {
        int blk = t >> 3, j = t & 7;
        float in[8], a[8];
        #pragma unroll
        for (int x = 0; x < 8; x++) in[x] = s1[blk][x][j];
        dct8_fwd(in, a);
        #pragma unroll
        for (int u = 0; u < 8; u++) s2[blk][u][j] = a[u];
    }
    __syncthreads();

    // ---- Stage B: horizontal DCT + diff_round quant + horizontal IDCT.
    if (t < 96) {
        int blk = t >> 3, u = t & 7;
        int ti = (blk < 8) ? 0 : 1;
        float row[8], cv[8];
        #pragma unroll
        for (int y = 0; y < 8; y++) row[y] = s2[blk][u][y];
        dct8_fwd(row, cv);

        // interleaved layout: lo half at u*4, hi half at 32 + u*4
        const float4 qa0 = *(const float4*)&sAq[ti][u * 4];
        const float4 qa1 = *(const float4*)&sAq[ti][u * 4 + 32];
        const float4 qb0 = *(const float4*)&sBq[ti][u * 4];
        const float4 qb1 = *(const float4*)&sBq[ti][u * 4 + 32];
        const float Aq[8]  = {qa0.x, qa0.y, qa0.z, qa0.w, qa1.x, qa1.y, qa1.z, qa1.w};
        const float Bq2[8] = {qb0.x, qb0.y, qb0.z, qb0.w, qb1.x, qb1.y, qb1.z, qb1.w};

        float h[8];
        #pragma unroll
        for (int v = 0; v < 8; v++) {
            float cc = cv[v] * Aq[v];
            float rr = rintf(cc);             // round-half-even == jnp.round
            float dd = cc - rr;
            h[v] = (rr + dd * dd * dd) * Bq2[v];
        }
        float p[8];
        dct8_inv(h, p);
        #pragma unroll
        for (int y = 0; y < 8; y++) s1[blk][u][y] = p[y];
    }
    __syncthreads();

    // ---- Stage C: vertical IDCT, output prescaled to the [0,1] domain.
    // Y: (p + 128)/255 as a single FFMA; chroma: p/255.
    if (t < 96) {
        int blk = t >> 3, j = t & 7;
        float in[8], p[8];
        #pragma unroll
        for (int u = 0; u < 8; u++) in[u] = s1[blk][u][j];
        dct8_inv(in, p);
        float add = (blk < 8) ? (128.f * INV255) : 0.f;
        #pragma unroll
        for (int x = 0; x < 8; x++) s2[blk][x][j] = p[x] * INV255 + add;
    }
    __syncthreads();

    // ---- Writeback: scalar shared reads, YCbCr->RGB, clip [0,1], store.
    float yv[4], cbv2[2], crv2[2];
    #pragma unroll
    for (int k = 0; k < 4; k++) yv[k] = s2[yblk][yrow][ycol + k];
    #pragma unroll
    for (int k = 0; k < 2; k++) {
        cbv2[k] = s2[8  + cbB][crow][ccol + k];
        crv2[k] = s2[10 + cbB][crow][ccol + k];
    }

    float Ro[4], Go[4], Bo[4];
    #pragma unroll
    for (int k = 0; k < 4; k++) {
        float yy = yv[k];
        float cb = cbv2[k >> 1];
        float cr = crv2[k >> 1];
        float rr = yy + 1.402f * cr;
        float gg = yy - 0.344136f * cb - 0.714136f * cr;
        float bb = yy + 1.772f * cb;
        Ro[k] = fminf(fmaxf(rr, 0.f), 1.f);
        Go[k] = fminf(fmaxf(gg, 0.f), 1.f);
        Bo[k] = fminf(fmaxf(bb, 0.f), 1.f);
    }
    float* op = out + (size_t)bimg * 3 * plane + (size_t)py * IMG + px0;
    *(float4*)(op)             = make_float4(Ro[0], Ro[1], Ro[2], Ro[3]);
    *(float4*)(op + plane)     = make_float4(Go[0], Go[1], Go[2], Go[3]);
    *(float4*)(op + 2 * plane) = make_float4(Bo[0], Bo[1], Bo[2], Bo[3]);
}

extern "C" void kernel_launch(void* const* d_in, const int* in_sizes, int n_in,
                              void* d_out, int out_size) {
    const float* img = (const float*)d_in[0];
    float* out = (float*)d_out;
    int batch = in_sizes[0] / (3 * IMG * IMG);         // 32
    int tiles = batch * (IMG / 16) * (IMG / 32);       // 16384
    jpeg_tile_kernel<<<tiles, 128>>>(img, out);
}

// round 17
// speedup vs baseline: 1.1109x; 1.0086x over previous
#include <cuda_runtime.h>
#include <math.h>

// ---------------------------------------------------------------------------
// Differentiable JPEG (quality 80) forward pass, fused single kernel. FINAL.
// Tile = 32x16 px, CTA = 128 threads; each thread owns a 1x4 row segment.
// Global I/O: float4. Shared staging: scalar on the conflict-free [8][9]
// layout. Quant tables interleaved (word = u*4 + (v&3) + (v>>2)*32) so every
// stage-B LDS.128 is a single conflict-free phase.
// Chroma 2x2 average: prescaled coefficients + shfl_xor(8) vertical pairing.
// Final /255 folded into stage C (FADD->FFMA, free); writeback clips [0,1].
// Session: 84.0 -> 41.1 us total (kernel 77.3 -> 39.1 us).
// ---------------------------------------------------------------------------

#define IMG 512

__constant__ float c_YTAB[64] = {
    16,11,10,16,24,40,51,61,  12,12,14,19,26,58,60,55,
    14,13,16,24,40,57,69,56,  14,17,22,29,51,87,80,62,
    18,22,37,56,68,109,103,77, 24,35,55,64,81,104,113,92,
    49,64,78,87,103,121,120,101, 72,92,95,98,112,100,103,99};
__constant__ float c_CTAB[64] = {
    17,18,24,47,99,99,99,99,  18,21,26,66,99,99,99,99,
    24,26,56,99,99,99,99,99,  47,66,99,99,99,99,99,99,
    99,99,99,99,99,99,99,99,  99,99,99,99,99,99,99,99,
    99,99,99,99,99,99,99,99,  99,99,99,99,99,99,99,99};

// cos(k*pi/16)
#define C1 0.980785280403230449f
#define C2 0.923879532511286756f
#define C3 0.831469612302545237f
#define C4 0.707106781186547524f
#define C5 0.555570233019602225f
#define C6 0.382683432365089772f
#define C7 0.195090322016128268f
#define RSQRT2 0.70710678118654752f
#define INV255 (1.0f / 255.0f)

__device__ __forceinline__ void dct8_fwd(const float in[8], float a[8]) {
    float s0 = in[0] + in[7], s1 = in[1] + in[6];
    float s2 = in[2] + in[5], s3 = in[3] + in[4];
    float d0 = in[0] - in[7], d1 = in[1] - in[6];
    float d2 = in[2] - in[5], d3 = in[3] - in[4];
    a[0] = (s0 + s3) + (s1 + s2);
    a[2] = C2 * s0 + C6 * s1 - C6 * s2 - C2 * s3;
    a[4] = C4 * ((s0 + s3) - (s1 + s2));
    a[6] = C6 * s0 - C2 * s1 + C2 * s2 - C6 * s3;
    a[1] = C1 * d0 + C3 * d1 + C5 * d2 + C7 * d3;
    a[3] = C3 * d0 - C7 * d1 - C1 * d2 - C5 * d3;
    a[5] = C5 * d0 - C1 * d1 + C7 * d2 + C3 * d3;
    a[7] = C7 * d0 - C5 * d1 + C3 * d2 - C1 * d3;
}

__device__ __forceinline__ void dct8_inv(const float h[8], float p[8]) {
    float e0 = h[0] + C2 * h[2] + C4 * h[4] + C6 * h[6];
    float e1 = h[0] + C6 * h[2] - C4 * h[4] - C2 * h[6];
    float e2 = h[0] - C6 * h[2] - C4 * h[4] + C2 * h[6];
    float e3 = h[0] - C2 * h[2] + C4 * h[4] - C6 * h[6];
    float o0 = C1 * h[1] + C3 * h[3] + C5 * h[5] + C7 * h[7];
    float o1 = C3 * h[1] - C7 * h[3] - C1 * h[5] - C5 * h[7];
    float o2 = C5 * h[1] - C1 * h[3] + C7 * h[5] + C3 * h[7];
    float o3 = C7 * h[1] - C5 * h[3] + C3 * h[5] - C1 * h[7];
    p[0] = e0 + o0;  p[7] = e0 - o0;
    p[1] = e1 + o1;  p[6] = e1 - o1;
    p[2] = e2 + o2;  p[5] = e2 - o2;
    p[3] = e3 + o3;  p[4] = e3 - o3;
}

__global__ void __launch_bounds__(128)
jpeg_tile_kernel(const float* __restrict__ img, float* __restrict__ out) {
    __shared__ float sAq[2][64];     // (ALPHA*0.25)/q, interleaved layout
    __shared__ float sBq[2][64];     // (ALPHA*0.25)*q, interleaved layout
    __shared__ float s1[12][8][9];   // blocks 0..7 = Y, 8..9 = Cb, 10..11 = Cr
    __shared__ float s2[12][8][9];

    const int t = threadIdx.x;

    if (t < 64) {
        int u = t >> 3, v = t & 7;
        float au = (u == 0) ? RSQRT2 : 1.f;
        float av = (v == 0) ? RSQRT2 : 1.f;
        float S = au * av * 0.25f;
        float qy = c_YTAB[t] * 0.4f;   // QUALITY=80 -> FACTOR=0.4
        float qc = c_CTAB[t] * 0.4f;
        // interleaved: word = u*4 + (v&3) + (v>>2)*32 -> LDS.128 at u*4 is
        // conflict-free across u (words 0..31 each hit once)
        int w = u * 4 + (v & 3) + ((v >> 2) << 5);
        sAq[0][w] = __fdividef(S, qy);  sBq[0][w] = S * qy;
        sAq[1][w] = __fdividef(S, qc);  sBq[1][w] = S * qc;
    }

    const int tile = blockIdx.x;
    const int tx   = tile & 15;          // 16 tiles across (32 px each)
    const int ty   = (tile >> 4) & 31;   // 32 tiles down (16 px each)
    const int bimg = tile >> 9;

    const int c = t & 7;                 // 4-px group 0..7 (32 px across)
    const int r = t >> 3;                // tile row 0..15
    const int px0 = tx * 32 + c * 4;
    const int py  = ty * 16 + r;

    const size_t plane = (size_t)IMG * IMG;
    const float* base = img + (size_t)bimg * 3 * plane + (size_t)py * IMG + px0;

    // Y block / position for this segment
    const int yblk = ((r >> 3) << 2) + (c >> 1);    // 4 across x 2 down
    const int ycol = (c & 1) * 4;
    const int yrow = r & 7;
    // Chroma block/col for this segment's 2 averaged px
    const int cbB  = c >> 2;                        // 0..1
    const int ccol = (c * 2) & 7;                   // 0,2,4,6 pattern
    const int crow = r >> 1;

    // ---- Pixel phase: float4 RGB loads, color-convert, scalar staging.
    float4 Rv4 = *(const float4*)(base);
    float4 Gv4 = *(const float4*)(base + plane);
    float4 Bv4 = *(const float4*)(base + 2 * plane);
    float Ra[4] = {Rv4.x, Rv4.y, Rv4.z, Rv4.w};
    float Ga[4] = {Gv4.x, Gv4.y, Gv4.z, Gv4.w};
    float Ba[4] = {Bv4.x, Bv4.y, Bv4.z, Bv4.w};

    float y4[4], cbp[2], crp[2];
    #pragma unroll
    for (int k = 0; k < 4; k++) {
        float rr = Ra[k] * 255.f, gg = Ga[k] * 255.f, bb = Ba[k] * 255.f;
        y4[k] = 0.299f * rr + 0.587f * gg + 0.114f * bb - 128.f;  // -128 folded
        // chroma coefficients prescaled by 0.25 (exact exponent shift)
        float cbv = -0.042184f * rr - 0.082816f * gg + 0.125f    * bb;
        float crv =  0.125f    * rr - 0.104672f * gg - 0.020328f * bb;
        if ((k & 1) == 0) { cbp[k >> 1] = cbv;  crp[k >> 1] = crv; }
        else              { cbp[k >> 1] += cbv; crp[k >> 1] += crv; }
    }
    // vertical pair: rows r, r^1 are lanes t, t^8 (same warp)
    #pragma unroll
    for (int k = 0; k < 2; k++) {
        cbp[k] += __shfl_xor_sync(0xFFFFFFFFu, cbp[k], 8);
        crp[k] += __shfl_xor_sync(0xFFFFFFFFu, crp[k], 8);
    }
    #pragma unroll
    for (int k = 0; k < 4; k++) s1[yblk][yrow][ycol + k] = y4[k];
    if ((r & 1) == 0) {
        #pragma unroll
        for (int k = 0; k < 2; k++) {
            s1[8  + cbB][crow][ccol + k] = cbp[k];
            s1[10 + cbB][crow][ccol + k] = crp[k];
        }
    }
    __syncthreads();

    // ---- Stage A: vertical DCT: s2[b][u][j] = sum_x CT[x][u]*s1[b][x][j]
    if (t < 96) {
        int blk = t >> 3, j = t & 7;
        float in[8], a[8];
        #pragma unroll
        for (int x = 0; x < 8; x++) in[x] = s1[blk][x][j];
        dct8_fwd(in, a);
        #pragma unroll
        for (int u = 0; u < 8; u++) s2[blk][u][j] = a[u];
    }
    __syncthreads();

    // ---- Stage B: horizontal DCT + diff_round quant + horizontal IDCT.
    if (t < 96) {
        int blk = t >> 3, u = t & 7;
        int ti = (blk < 8) ? 0 : 1;
        float row[8], cv[8];
        #pragma unroll
        for (int y = 0; y < 8; y++) row[y] = s2[blk][u][y];
        dct8_fwd(row, cv);

        // interleaved layout: lo half at u*4, hi half at 32 + u*4
        const float4 qa0 = *(const float4*)&sAq[ti][u * 4];
        const float4 qa1 = *(const float4*)&sAq[ti][u * 4 + 32];
        const float4 qb0 = *(const float4*)&sBq[ti][u * 4];
        const float4 qb1 = *(const float4*)&sBq[ti][u * 4 + 32];
        const float Aq[8]  = {qa0.x, qa0.y, qa0.z, qa0.w, qa1.x, qa1.y, qa1.z, qa1.w};
        const float Bq2[8] = {qb0.x, qb0.y, qb0.z, qb0.w, qb1.x, qb1.y, qb1.z, qb1.w};

        float h[8];
        #pragma unroll
        for (int v = 0; v < 8; v++) {
            float cc = cv[v] * Aq[v];
            float rr = rintf(cc);             // round-half-even == jnp.round
            float dd = cc - rr;
            h[v] = (rr + dd * dd * dd) * Bq2[v];
        }
        float p[8];
        dct8_inv(h, p);
        #pragma unroll
        for (int y = 0; y < 8; y++) s1[blk][u][y] = p[y];
    }
    __syncthreads();

    // ---- Stage C: vertical IDCT, output prescaled to the [0,1] domain.
    // Y: (p + 128)/255 as a single FFMA; chroma: p/255.
    if (t < 96) {
        int blk = t >> 3, j = t & 7;
        float in[8], p[8];
        #pragma unroll
        for (int u = 0; u < 8; u++) in[u] = s1[blk][u][j];
        dct8_inv(in, p);
        float add = (blk < 8) ? (128.f * INV255) : 0.f;
        #pragma unroll
        for (int x = 0; x < 8; x++) s2[blk][x][j] = p[x] * INV255 + add;
    }
    __syncthreads();

    // ---- Writeback: scalar shared reads, YCbCr->RGB, clip [0,1], store.
    float yv[4], cbv2[2], crv2[2];
    #pragma unroll
    for (int k = 0; k < 4; k++) yv[k] = s2[yblk][yrow][ycol + k];
    #pragma unroll
    for (int k = 0; k < 2; k++) {
        cbv2[k] = s2[8  + cbB][crow][ccol + k];
        crv2[k] = s2[10 + cbB][crow][ccol + k];
    }

    float Ro[4], Go[4], Bo[4];
    #pragma unroll
    for (int k = 0; k < 4; k++) {
        float yy = yv[k];
        float cb = cbv2[k >> 1];
        float cr = crv2[k >> 1];
        float rr = yy + 1.402f * cr;
        float gg = yy - 0.344136f * cb - 0.714136f * cr;
        float bb = yy + 1.772f * cb;
        Ro[k] = fminf(fmaxf(rr, 0.f), 1.f);
        Go[k] = fminf(fmaxf(gg, 0.f), 1.f);
        Bo[k] = fminf(fmaxf(bb, 0.f), 1.f);
    }
    float* op = out + (size_t)bimg * 3 * plane + (size_t)py * IMG + px0;
    *(float4*)(op)             = make_float4(Ro[0], Ro[1], Ro[2], Ro[3]);
    *(float4*)(op + plane)     = make_float4(Go[0], Go[1], Go[2], Go[3]);
    *(float4*)(op + 2 * plane) = make_float4(Bo[0], Bo[1], Bo[2], Bo[3]);
}

extern "C" void kernel_launch(void* const* d_in, const int* in_sizes, int n_in,
                              void* d_out, int out_size) {
    const float* img = (const float*)d_in[0];
    float* out = (float*)d_out;
    int batch = in_sizes[0] / (3 * IMG * IMG);         // 32
    int tiles = batch * (IMG / 16) * (IMG / 32);       // 16384
    jpeg_tile_kernel<<<tiles, 128>>>(img, out);
}